// round 3
// baseline (speedup 1.0000x reference)
#include <cuda_runtime.h>

#define NN 4096
#define NF 512
#define NH 60
#define NC 4
#define MAXDEG 128

// ---- static device scratch (no allocations allowed) ----
__device__ float g_d[NN];            // column sums of A_tilde (init 1.0 for self loop)
__device__ float g_dis[NN];          // d^{-1/2}
__device__ int   g_cnt[NN];          // per-row nnz count
__device__ int   g_col[NN * MAXDEG]; // slotted CSR columns
__device__ float g_wv[NN * MAXDEG];  // slotted CSR values (sigmoid(P)*adj)
__device__ float g_bufA[NN * NH];
__device__ float g_bufB[NN * NH];

// ---------------- kernel 1: init ----------------
__global__ void k_init() {
    int i = blockIdx.x * blockDim.x + threadIdx.x;
    if (i < NN) { g_d[i] = 1.0f; g_cnt[i] = 0; }
}

// ---------------- kernel 2: scan sub_adj, build sparse A_tilde ----------------
// Entry (i,j): w = sigmoid(P_hat_symm[i,j]) * sub_adj[i,j]
// P_hat_symm[i,j] = P_vec[tri(i,j)] with tri = lower-tri row-major index.
__global__ void k_scan(const float4* __restrict__ adj, const float* __restrict__ P) {
    int stride = gridDim.x * blockDim.x;
    const int NV = NN * NN / 4;
    for (int v = blockIdx.x * blockDim.x + threadIdx.x; v < NV; v += stride) {
        float4 a4 = adj[v];
        if (a4.x == 0.f && a4.y == 0.f && a4.z == 0.f && a4.w == 0.f) continue;
        int base = v << 2;
        int i = base >> 12;          // / 4096
        int j0 = base & (NN - 1);
        float av[4] = {a4.x, a4.y, a4.z, a4.w};
        #pragma unroll
        for (int t = 0; t < 4; t++) {
            float a = av[t];
            if (a == 0.f) continue;
            int j = j0 + t;
            int tri = (i >= j) ? (i * (i + 1) / 2 + j) : (j * (j + 1) / 2 + i);
            float p = P[tri];
            float w = a / (1.f + __expf(-p));   // sigmoid(p) * a
            atomicAdd(&g_d[j], w);              // column sum
            int s = atomicAdd(&g_cnt[i], 1);    // spread over 4096 addrs
            if (s < MAXDEG) {
                g_col[i * MAXDEG + s] = j;
                g_wv[i * MAXDEG + s] = w;
            }
        }
    }
}

// ---------------- kernel 3: Z0 = X @ W1  (+ dis prologue) ----------------
// 240 threads: 15 col-groups (4 cols) x 16 row-threads (2 rows). 32 rows/block.
__global__ void __launch_bounds__(240) k_gemm1(const float* __restrict__ X,
                                               const float* __restrict__ W1) {
    __shared__ float Xs[32 * 68];   // stride 68 (mult of 4, not 32) avoids bank conflicts
    __shared__ float Ws[64 * NH];
    int tid = threadIdx.x;

    // fused dis prologue (read by later kernels only)
    int gid = blockIdx.x * 240 + tid;
    if (gid < NN) g_dis[gid] = rsqrtf(g_d[gid]);

    int cg = tid % 15, rt = tid / 15;
    int c0 = cg * 4;
    int r0 = rt * 2;
    int rowbase = blockIdx.x * 32;

    float acc00 = 0.f, acc01 = 0.f, acc02 = 0.f, acc03 = 0.f;
    float acc10 = 0.f, acc11 = 0.f, acc12 = 0.f, acc13 = 0.f;

    for (int kb = 0; kb < NF; kb += 64) {
        // stage X tile: 32 rows x 64 k = 512 float4
        for (int idx = tid; idx < 512; idx += 240) {
            int r = idx >> 4, k4 = idx & 15;
            float4 x = *(const float4*)&X[(rowbase + r) * NF + kb + k4 * 4];
            *(float4*)&Xs[r * 68 + k4 * 4] = x;
        }
        // stage W tile: rows kb..kb+63 (all 60 cols) = contiguous 3840 floats
        const float4* Wsrc = (const float4*)&W1[kb * NH];
        for (int idx = tid; idx < 960; idx += 240)
            *((float4*)Ws + idx) = Wsrc[idx];
        __syncthreads();

        #pragma unroll 8
        for (int kk = 0; kk < 64; kk++) {
            float4 w = *(const float4*)&Ws[kk * NH + c0];
            float x0 = Xs[r0 * 68 + kk];
            float x1 = Xs[(r0 + 1) * 68 + kk];
            acc00 += x0 * w.x; acc01 += x0 * w.y; acc02 += x0 * w.z; acc03 += x0 * w.w;
            acc10 += x1 * w.x; acc11 += x1 * w.y; acc12 += x1 * w.z; acc13 += x1 * w.w;
        }
        __syncthreads();
    }
    *(float4*)&g_bufA[(rowbase + r0)     * NH + c0] = make_float4(acc00, acc01, acc02, acc03);
    *(float4*)&g_bufA[(rowbase + r0 + 1) * NH + c0] = make_float4(acc10, acc11, acc12, acc13);
}

// ---------------- kernels 4-6: SpMM (+bias[,relu]) fused with next GEMM / head ----------------
// MODE 0: h = relu(spmm(Zin)+bias); out = h @ Wn   (Wn is NH x NH)
// MODE 1: h = spmm(Zin)+bias; logits = h @ Wn + lin_b (Wn is NH x NC); out = log_softmax
template <int MODE>
__global__ void __launch_bounds__(256) k_spmm(const float* __restrict__ Zin,
                                              const float* __restrict__ bias,
                                              const float* __restrict__ Wn,
                                              const float* __restrict__ lin_b,
                                              float* __restrict__ out) {
    __shared__ float Wsh[NH * NH];
    __shared__ float hsh[8][64];
    int tid = threadIdx.x;
    const int wcount = (MODE == 0) ? NH * NH : NH * NC;
    for (int idx = tid; idx < wcount; idx += 256) Wsh[idx] = Wn[idx];
    __syncthreads();

    int w = tid >> 5, lane = tid & 31;
    int row = blockIdx.x * 8 + w;
    int deg = min(g_cnt[row], MAXDEG);
    const int base = row * MAXDEG;

    float a0 = 0.f, a1 = 0.f;
    for (int e = 0; e < deg; e++) {
        int j = g_col[base + e];                 // uniform per warp (broadcast)
        float cw = g_wv[base + e] * g_dis[j];
        a0 += cw * Zin[j * NH + lane];
        if (lane < NH - 32) a1 += cw * Zin[j * NH + 32 + lane];
    }
    float di = g_dis[row];
    float d2 = di * di;
    float h0 = di * a0 + d2 * Zin[row * NH + lane] + bias[lane];
    float h1 = 0.f;
    if (lane < NH - 32)
        h1 = di * a1 + d2 * Zin[row * NH + 32 + lane] + bias[32 + lane];
    if (MODE == 0) { h0 = fmaxf(h0, 0.f); h1 = fmaxf(h1, 0.f); }
    hsh[w][lane] = h0;
    if (lane < NH - 32) hsh[w][32 + lane] = h1;
    __syncwarp();

    if (MODE == 0) {
        float z0 = 0.f, z1 = 0.f;
        #pragma unroll
        for (int k = 0; k < NH; k++) {
            float hk = hsh[w][k];                // broadcast
            z0 += hk * Wsh[k * NH + lane];       // conflict-free
            if (lane < NH - 32) z1 += hk * Wsh[k * NH + 32 + lane];
        }
        out[row * NH + lane] = z0;
        if (lane < NH - 32) out[row * NH + 32 + lane] = z1;
    } else {
        float logit = 0.f;
        if (lane < NC) {
            logit = lin_b[lane];
            #pragma unroll
            for (int k = 0; k < NH; k++) logit += hsh[w][k] * Wsh[k * NC + lane];
        }
        float l0 = __shfl_sync(0xffffffffu, logit, 0);
        float l1 = __shfl_sync(0xffffffffu, logit, 1);
        float l2 = __shfl_sync(0xffffffffu, logit, 2);
        float l3 = __shfl_sync(0xffffffffu, logit, 3);
        if (lane < NC) {
            float m = fmaxf(fmaxf(l0, l1), fmaxf(l2, l3));
            float s = __expf(l0 - m) + __expf(l1 - m) + __expf(l2 - m) + __expf(l3 - m);
            out[row * NC + lane] = logit - m - logf(s);
        }
    }
}

// ---------------- launch ----------------
extern "C" void kernel_launch(void* const* d_in, const int* in_sizes, int n_in,
                              void* d_out, int out_size) {
    const float* x     = (const float*)d_in[0];
    const float* adj   = (const float*)d_in[1];
    const float* P     = (const float*)d_in[2];
    const float* W1    = (const float*)d_in[3];
    const float* b1    = (const float*)d_in[4];
    const float* W2    = (const float*)d_in[5];
    const float* b2    = (const float*)d_in[6];
    const float* W3    = (const float*)d_in[7];
    const float* b3    = (const float*)d_in[8];
    const float* lin_w = (const float*)d_in[9];
    const float* lin_b = (const float*)d_in[10];
    float* out = (float*)d_out;

    float *bufA, *bufB;
    cudaGetSymbolAddress((void**)&bufA, g_bufA);
    cudaGetSymbolAddress((void**)&bufB, g_bufB);

    k_init<<<16, 256>>>();
    k_scan<<<1024, 256>>>((const float4*)adj, P);
    k_gemm1<<<128, 240>>>(x, W1);                               // bufA = X@W1, dis
    k_spmm<0><<<512, 256>>>(bufA, b1, W2, nullptr, bufB);       // bufB = relu(spmm+b1)@W2
    k_spmm<0><<<512, 256>>>(bufB, b2, W3, nullptr, bufA);       // bufA = relu(spmm+b2)@W3
    k_spmm<1><<<512, 256>>>(bufA, b3, lin_w, lin_b, out);       // log_softmax head
}

// round 5
// speedup vs baseline: 1.4175x; 1.4175x over previous
#include <cuda_runtime.h>

#define NN 4096
#define NF 512
#define NH 60
#define NC 4
#define MAXDEG 128
#define PAD 64   // padded feature stride

// ---- static device scratch (no allocations allowed) ----
__device__ float  g_d[NN];              // column sums of A_tilde (init 1.0 for self loop)
__device__ int    g_cnt[NN];            // per-row nnz count
__device__ int    g_col[NN * MAXDEG];   // raw CSR columns (from scan)
__device__ float  g_wv[NN * MAXDEG];    // raw CSR values (sigmoid(P)*adj)
__device__ float2 g_edge[NN * MAXDEG];  // prescaled edges: {bitcast(j), w*dis_i*dis_j}
__device__ float  g_self[NN];           // 1/d_i  (self-loop weight dis_i^2)
__device__ float  g_bufA[NN * PAD];
__device__ float  g_bufB[NN * PAD];

// ---------------- kernel 1: init ----------------
__global__ void k_init() {
    int i = blockIdx.x * blockDim.x + threadIdx.x;
    if (i < NN) {
        g_d[i] = 1.0f; g_cnt[i] = 0;
        // zero padding columns (gemm1 only writes 0..59)
        #pragma unroll
        for (int c = NH; c < PAD; c++) {
            g_bufA[i * PAD + c] = 0.f;
            g_bufB[i * PAD + c] = 0.f;
        }
    }
}

// ---------------- kernel 2: scan sub_adj ----------------
// 8 front-batched float4 loads per thread (MLP=8), strided so each chunk is coalesced.
__global__ void __launch_bounds__(256) k_scan(const float4* __restrict__ adj,
                                              const float* __restrict__ P) {
    const int T = 2048 * 256;
    int t = blockIdx.x * 256 + threadIdx.x;
    float4 a[8];
    #pragma unroll
    for (int u = 0; u < 8; u++) a[u] = adj[t + u * T];

    #pragma unroll
    for (int u = 0; u < 8; u++) {
        float4 a4 = a[u];
        if (a4.x == 0.f && a4.y == 0.f && a4.z == 0.f && a4.w == 0.f) continue;
        int base = (t + u * T) << 2;
        int i = base >> 12;
        int j0 = base & (NN - 1);
        float av[4] = {a4.x, a4.y, a4.z, a4.w};
        #pragma unroll
        for (int q = 0; q < 4; q++) {
            float aa = av[q];
            if (aa == 0.f) continue;
            int j = j0 + q;
            int tri = (i >= j) ? (i * (i + 1) / 2 + j) : (j * (j + 1) / 2 + i);
            float p = P[tri];
            float w = aa / (1.f + __expf(-p));
            atomicAdd(&g_d[j], w);
            int s = atomicAdd(&g_cnt[i], 1);
            if (s < MAXDEG) {
                g_col[i * MAXDEG + s] = j;
                g_wv[i * MAXDEG + s] = w;
            }
        }
    }
}

// ---------------- kernel 3: prescale edges ----------------
// one warp per row: edge_w = w * rsqrt(d_i) * rsqrt(d_j); self = 1/d_i.
__global__ void __launch_bounds__(256) k_prep() {
    int tid = threadIdx.x;
    int w = tid >> 5, lane = tid & 31;
    int row = blockIdx.x * 8 + w;
    float ri = rsqrtf(g_d[row]);
    if (lane == 0) g_self[row] = ri * ri;
    int deg = min(g_cnt[row], MAXDEG);
    int base = row * MAXDEG;
    for (int e = lane; e < deg; e += 32) {
        int j = g_col[base + e];
        float ww = g_wv[base + e] * ri * rsqrtf(g_d[j]);
        g_edge[base + e] = make_float2(__int_as_float(j), ww);
    }
}

// ---------------- kernel 4: Z0 = X @ W1 ----------------
// 240 threads: 15 col-groups (4 cols) x 16 row-threads (2 rows). 32 rows/block.
__global__ void __launch_bounds__(240) k_gemm1(const float* __restrict__ X,
                                               const float* __restrict__ W1) {
    __shared__ float Xs[32 * 68];
    __shared__ float Ws[64 * NH];
    int tid = threadIdx.x;
    int cg = tid % 15, rt = tid / 15;
    int c0 = cg * 4;
    int r0 = rt * 2;
    int rowbase = blockIdx.x * 32;

    float acc00 = 0.f, acc01 = 0.f, acc02 = 0.f, acc03 = 0.f;
    float acc10 = 0.f, acc11 = 0.f, acc12 = 0.f, acc13 = 0.f;

    for (int kb = 0; kb < NF; kb += 64) {
        for (int idx = tid; idx < 512; idx += 240) {
            int r = idx >> 4, k4 = idx & 15;
            float4 x = *(const float4*)&X[(rowbase + r) * NF + kb + k4 * 4];
            *(float4*)&Xs[r * 68 + k4 * 4] = x;
        }
        const float4* Wsrc = (const float4*)&W1[kb * NH];
        for (int idx = tid; idx < 960; idx += 240)
            *((float4*)Ws + idx) = Wsrc[idx];
        __syncthreads();

        #pragma unroll 8
        for (int kk = 0; kk < 64; kk++) {
            float4 w = *(const float4*)&Ws[kk * NH + c0];
            float x0 = Xs[r0 * 68 + kk];
            float x1 = Xs[(r0 + 1) * 68 + kk];
            acc00 += x0 * w.x; acc01 += x0 * w.y; acc02 += x0 * w.z; acc03 += x0 * w.w;
            acc10 += x1 * w.x; acc11 += x1 * w.y; acc12 += x1 * w.z; acc13 += x1 * w.w;
        }
        __syncthreads();
    }
    *(float4*)&g_bufA[(rowbase + r0)     * PAD + c0] = make_float4(acc00, acc01, acc02, acc03);
    *(float4*)&g_bufA[(rowbase + r0 + 1) * PAD + c0] = make_float4(acc10, acc11, acc12, acc13);
}

// ---------------- kernels 5-7: SpMM (+bias[,relu]) fused with next GEMM / head ----------------
// Zin/out are PAD(64)-strided; each lane owns feature cols {2*lane, 2*lane+1} as float2.
template <int MODE>
__global__ void __launch_bounds__(256) k_spmm(const float* __restrict__ Zin,
                                              const float* __restrict__ bias,
                                              const float* __restrict__ Wn,
                                              const float* __restrict__ lin_b,
                                              float* __restrict__ out) {
    __shared__ float Wsh[NH * PAD];      // zero-padded: Wsh[k*64 + c]
    __shared__ float hsh[8][PAD];
    int tid = threadIdx.x;

    if (MODE == 0) {
        for (int idx = tid; idx < NH * PAD; idx += 256) {
            int k = idx >> 6, c = idx & 63;
            Wsh[idx] = (c < NH) ? Wn[k * NH + c] : 0.f;
        }
    } else {
        for (int idx = tid; idx < NH * NC; idx += 256) Wsh[idx] = Wn[idx];
    }
    __syncthreads();

    int w = tid >> 5, lane = tid & 31;
    int row = blockIdx.x * 8 + w;
    int deg = min(g_cnt[row], MAXDEG);
    const float2* ep = g_edge + row * MAXDEG;
    const float2* Z2 = (const float2*)Zin;

    float2 acc = make_float2(0.f, 0.f);
    int e = 0;
    for (; e + 4 <= deg; e += 4) {
        float2 q0 = ep[e], q1 = ep[e + 1], q2 = ep[e + 2], q3 = ep[e + 3];
        int j0 = __float_as_int(q0.x), j1 = __float_as_int(q1.x);
        int j2 = __float_as_int(q2.x), j3 = __float_as_int(q3.x);
        float2 z0 = Z2[j0 * 32 + lane];
        float2 z1 = Z2[j1 * 32 + lane];
        float2 z2 = Z2[j2 * 32 + lane];
        float2 z3 = Z2[j3 * 32 + lane];
        acc.x += q0.y * z0.x + q1.y * z1.x + q2.y * z2.x + q3.y * z3.x;
        acc.y += q0.y * z0.y + q1.y * z1.y + q2.y * z2.y + q3.y * z3.y;
    }
    for (; e < deg; e++) {
        float2 q = ep[e];
        int j = __float_as_int(q.x);
        float2 z = Z2[j * 32 + lane];
        acc.x += q.y * z.x;
        acc.y += q.y * z.y;
    }

    float2 h = make_float2(0.f, 0.f);
    if (lane < NH / 2) {
        float sw = g_self[row];
        float2 zr = Z2[row * 32 + lane];
        float2 bi = ((const float2*)bias)[lane];
        h.x = acc.x + sw * zr.x + bi.x;
        h.y = acc.y + sw * zr.y + bi.y;
        if (MODE == 0) { h.x = fmaxf(h.x, 0.f); h.y = fmaxf(h.y, 0.f); }
    }
    *(float2*)&hsh[w][2 * lane] = h;
    __syncwarp();

    if (MODE == 0) {
        const float2* Wsh2 = (const float2*)Wsh;
        float2 z = make_float2(0.f, 0.f);
        #pragma unroll
        for (int k = 0; k < NH; k++) {
            float hk = hsh[w][k];               // broadcast
            float2 wv = Wsh2[k * 32 + lane];    // conflict-free, pad lanes read zeros
            z.x += hk * wv.x;
            z.y += hk * wv.y;
        }
        ((float2*)out)[row * 32 + lane] = z;    // pad lanes write zeros
    } else {
        float logit = 0.f;
        if (lane < NC) {
            logit = lin_b[lane];
            #pragma unroll
            for (int k = 0; k < NH; k++) logit += hsh[w][k] * Wsh[k * NC + lane];
        }
        float l0 = __shfl_sync(0xffffffffu, logit, 0);
        float l1 = __shfl_sync(0xffffffffu, logit, 1);
        float l2 = __shfl_sync(0xffffffffu, logit, 2);
        float l3 = __shfl_sync(0xffffffffu, logit, 3);
        if (lane < NC) {
            float m = fmaxf(fmaxf(l0, l1), fmaxf(l2, l3));
            float s = __expf(l0 - m) + __expf(l1 - m) + __expf(l2 - m) + __expf(l3 - m);
            out[row * NC + lane] = logit - m - logf(s);
        }
    }
}

// ---------------- launch ----------------
extern "C" void kernel_launch(void* const* d_in, const int* in_sizes, int n_in,
                              void* d_out, int out_size) {
    const float* x     = (const float*)d_in[0];
    const float* adj   = (const float*)d_in[1];
    const float* P     = (const float*)d_in[2];
    const float* W1    = (const float*)d_in[3];
    const float* b1    = (const float*)d_in[4];
    const float* W2    = (const float*)d_in[5];
    const float* b2    = (const float*)d_in[6];
    const float* W3    = (const float*)d_in[7];
    const float* b3    = (const float*)d_in[8];
    const float* lin_w = (const float*)d_in[9];
    const float* lin_b = (const float*)d_in[10];
    float* out = (float*)d_out;

    float *bufA, *bufB;
    cudaGetSymbolAddress((void**)&bufA, g_bufA);
    cudaGetSymbolAddress((void**)&bufB, g_bufB);

    k_init<<<16, 256>>>();
    k_scan<<<2048, 256>>>((const float4*)adj, P);
    k_prep<<<512, 256>>>();
    k_gemm1<<<128, 240>>>(x, W1);                               // bufA = X@W1 (64-pad)
    k_spmm<0><<<512, 256>>>(bufA, b1, W2, nullptr, bufB);       // bufB = relu(spmm+b1)@W2
    k_spmm<0><<<512, 256>>>(bufB, b2, W3, nullptr, bufA);       // bufA = relu(spmm+b2)@W3
    k_spmm<1><<<512, 256>>>(bufA, b3, lin_w, lin_b, out);       // log_softmax head
}

// round 7
// speedup vs baseline: 1.6315x; 1.1510x over previous
#include <cuda_runtime.h>

#define NN 4096
#define NF 512
#define NH 60
#define NC 4
#define MAXDEG 128
#define PAD 64   // padded feature stride

// ---- static device scratch (no allocations allowed) ----
__device__ float  g_d[NN];              // column sums of A_tilde (init 1.0 for self loop)
__device__ int    g_cnt[NN];            // per-row nnz count
__device__ int    g_col[NN * MAXDEG];   // raw CSR columns (from scan)
__device__ float  g_wv[NN * MAXDEG];    // raw CSR values (sigmoid(P)*adj)
__device__ float2 g_edge[NN * MAXDEG];  // prescaled edges: {bitcast(j), w*dis_i*dis_j}
__device__ float  g_self[NN];           // 1/d_i  (self-loop weight dis_i^2)
__device__ float  g_bufA[NN * PAD];
__device__ float  g_bufB[NN * PAD];

// ---------------- kernel 1: init ----------------
// Zeroes ALL of bufA (gemm1 accumulates into it with atomics), bufB pads,
// and resets degree/count arrays.
__global__ void k_init() {
    int t = blockIdx.x * blockDim.x + threadIdx.x;   // 65536 threads
    ((float4*)g_bufA)[t] = make_float4(0.f, 0.f, 0.f, 0.f);
    if (t < NN) {
        g_d[t] = 1.0f; g_cnt[t] = 0;
        #pragma unroll
        for (int c = NH; c < PAD; c++) g_bufB[t * PAD + c] = 0.f;
    }
}

// ---------------- kernel 2: scan sub_adj ----------------
// 8 front-batched float4 loads per thread (MLP=8), strided so each chunk is coalesced.
__global__ void __launch_bounds__(256) k_scan(const float4* __restrict__ adj,
                                              const float* __restrict__ P) {
    const int T = 2048 * 256;
    int t = blockIdx.x * 256 + threadIdx.x;
    float4 a[8];
    #pragma unroll
    for (int u = 0; u < 8; u++) a[u] = adj[t + u * T];

    #pragma unroll
    for (int u = 0; u < 8; u++) {
        float4 a4 = a[u];
        if (a4.x == 0.f && a4.y == 0.f && a4.z == 0.f && a4.w == 0.f) continue;
        int base = (t + u * T) << 2;
        int i = base >> 12;
        int j0 = base & (NN - 1);
        float av[4] = {a4.x, a4.y, a4.z, a4.w};
        #pragma unroll
        for (int q = 0; q < 4; q++) {
            float aa = av[q];
            if (aa == 0.f) continue;
            int j = j0 + q;
            int tri = (i >= j) ? (i * (i + 1) / 2 + j) : (j * (j + 1) / 2 + i);
            float p = P[tri];
            float w = aa / (1.f + __expf(-p));
            atomicAdd(&g_d[j], w);
            int s = atomicAdd(&g_cnt[i], 1);
            if (s < MAXDEG) {
                g_col[i * MAXDEG + s] = j;
                g_wv[i * MAXDEG + s] = w;
            }
        }
    }
}

// ---------------- kernel 3: prescale edges ----------------
// one warp per row: edge_w = w * rsqrt(d_i) * rsqrt(d_j); self = 1/d_i.
__global__ void __launch_bounds__(256) k_prep() {
    int tid = threadIdx.x;
    int w = tid >> 5, lane = tid & 31;
    int row = blockIdx.x * 8 + w;
    float ri = rsqrtf(g_d[row]);
    if (lane == 0) g_self[row] = ri * ri;
    int deg = min(g_cnt[row], MAXDEG);
    int base = row * MAXDEG;
    for (int e = lane; e < deg; e += 32) {
        int j = g_col[base + e];
        float ww = g_wv[base + e] * ri * rsqrtf(g_d[j]);
        g_edge[base + e] = make_float2(__int_as_float(j), ww);
    }
}

// ---------------- kernel 4: Z0 = X @ W1 (K-split, atomic accumulate) ----------------
// grid = (128 row-blocks, 4 K-chunks). Each block: 32 rows x 60 cols over K=128.
// 240 threads: 15 col-groups (4 cols) x 16 row-threads (2 rows).
__global__ void __launch_bounds__(240) k_gemm1(const float* __restrict__ X,
                                               const float* __restrict__ W1) {
    __shared__ float Xs[32 * 68];
    __shared__ float Ws[64 * NH];
    int tid = threadIdx.x;
    int cg = tid % 15, rt = tid / 15;
    int c0 = cg * 4;
    int r0 = rt * 2;
    int rowbase = blockIdx.x * 32;
    int kbase = blockIdx.y * 128;

    float acc00 = 0.f, acc01 = 0.f, acc02 = 0.f, acc03 = 0.f;
    float acc10 = 0.f, acc11 = 0.f, acc12 = 0.f, acc13 = 0.f;

    for (int kb = kbase; kb < kbase + 128; kb += 64) {
        for (int idx = tid; idx < 512; idx += 240) {
            int r = idx >> 4, k4 = idx & 15;
            float4 x = *(const float4*)&X[(rowbase + r) * NF + kb + k4 * 4];
            *(float4*)&Xs[r * 68 + k4 * 4] = x;
        }
        const float4* Wsrc = (const float4*)&W1[kb * NH];
        for (int idx = tid; idx < 960; idx += 240)
            *((float4*)Ws + idx) = Wsrc[idx];
        __syncthreads();

        #pragma unroll 8
        for (int kk = 0; kk < 64; kk++) {
            float4 w = *(const float4*)&Ws[kk * NH + c0];
            float x0 = Xs[r0 * 68 + kk];
            float x1 = Xs[(r0 + 1) * 68 + kk];
            acc00 += x0 * w.x; acc01 += x0 * w.y; acc02 += x0 * w.z; acc03 += x0 * w.w;
            acc10 += x1 * w.x; acc11 += x1 * w.y; acc12 += x1 * w.z; acc13 += x1 * w.w;
        }
        __syncthreads();
    }
    float* o0 = &g_bufA[(rowbase + r0)     * PAD + c0];
    float* o1 = &g_bufA[(rowbase + r0 + 1) * PAD + c0];
    atomicAdd(o0 + 0, acc00); atomicAdd(o0 + 1, acc01);
    atomicAdd(o0 + 2, acc02); atomicAdd(o0 + 3, acc03);
    atomicAdd(o1 + 0, acc10); atomicAdd(o1 + 1, acc11);
    atomicAdd(o1 + 2, acc12); atomicAdd(o1 + 3, acc13);
}

// ---------------- kernels 5-7: SpMM (+bias[,relu]) fused with next GEMM / head ----------------
// Zin/out are PAD(64)-strided; each lane owns feature cols {2*lane, 2*lane+1} as float2.
template <int MODE>
__global__ void __launch_bounds__(256) k_spmm(const float* __restrict__ Zin,
                                              const float* __restrict__ bias,
                                              const float* __restrict__ Wn,
                                              const float* __restrict__ lin_b,
                                              float* __restrict__ out) {
    __shared__ float Wsh[NH * PAD];      // zero-padded: Wsh[k*64 + c]
    __shared__ float hsh[8][PAD];
    int tid = threadIdx.x;

    if (MODE == 0) {
        for (int idx = tid; idx < NH * PAD; idx += 256) {
            int k = idx >> 6, c = idx & 63;
            Wsh[idx] = (c < NH) ? Wn[k * NH + c] : 0.f;
        }
    } else {
        for (int idx = tid; idx < NH * NC; idx += 256) Wsh[idx] = Wn[idx];
    }
    __syncthreads();

    int w = tid >> 5, lane = tid & 31;
    int row = blockIdx.x * 8 + w;
    int deg = min(g_cnt[row], MAXDEG);
    const float2* ep = g_edge + row * MAXDEG;
    const float2* Z2 = (const float2*)Zin;

    float2 acc = make_float2(0.f, 0.f);
    int e = 0;
    for (; e + 4 <= deg; e += 4) {
        float2 q0 = ep[e], q1 = ep[e + 1], q2 = ep[e + 2], q3 = ep[e + 3];
        int j0 = __float_as_int(q0.x), j1 = __float_as_int(q1.x);
        int j2 = __float_as_int(q2.x), j3 = __float_as_int(q3.x);
        float2 z0 = Z2[j0 * 32 + lane];
        float2 z1 = Z2[j1 * 32 + lane];
        float2 z2 = Z2[j2 * 32 + lane];
        float2 z3 = Z2[j3 * 32 + lane];
        acc.x += q0.y * z0.x + q1.y * z1.x + q2.y * z2.x + q3.y * z3.x;
        acc.y += q0.y * z0.y + q1.y * z1.y + q2.y * z2.y + q3.y * z3.y;
    }
    for (; e < deg; e++) {
        float2 q = ep[e];
        int j = __float_as_int(q.x);
        float2 z = Z2[j * 32 + lane];
        acc.x += q.y * z.x;
        acc.y += q.y * z.y;
    }

    float2 h = make_float2(0.f, 0.f);
    if (lane < NH / 2) {
        float sw = g_self[row];
        float2 zr = Z2[row * 32 + lane];
        float2 bi = ((const float2*)bias)[lane];
        h.x = acc.x + sw * zr.x + bi.x;
        h.y = acc.y + sw * zr.y + bi.y;
        if (MODE == 0) { h.x = fmaxf(h.x, 0.f); h.y = fmaxf(h.y, 0.f); }
    }
    *(float2*)&hsh[w][2 * lane] = h;
    __syncwarp();

    if (MODE == 0) {
        const float2* Wsh2 = (const float2*)Wsh;
        float2 z = make_float2(0.f, 0.f);
        #pragma unroll
        for (int k = 0; k < NH; k++) {
            float hk = hsh[w][k];               // broadcast
            float2 wv = Wsh2[k * 32 + lane];    // conflict-free, pad lanes read zeros
            z.x += hk * wv.x;
            z.y += hk * wv.y;
        }
        ((float2*)out)[row * 32 + lane] = z;    // pad lanes write zeros
    } else {
        float logit = 0.f;
        if (lane < NC) {
            logit = lin_b[lane];
            #pragma unroll
            for (int k = 0; k < NH; k++) logit += hsh[w][k] * Wsh[k * NC + lane];
        }
        float l0 = __shfl_sync(0xffffffffu, logit, 0);
        float l1 = __shfl_sync(0xffffffffu, logit, 1);
        float l2 = __shfl_sync(0xffffffffu, logit, 2);
        float l3 = __shfl_sync(0xffffffffu, logit, 3);
        if (lane < NC) {
            float m = fmaxf(fmaxf(l0, l1), fmaxf(l2, l3));
            float s = __expf(l0 - m) + __expf(l1 - m) + __expf(l2 - m) + __expf(l3 - m);
            out[row * NC + lane] = logit - m - logf(s);
        }
    }
}

// ---------------- launch ----------------
extern "C" void kernel_launch(void* const* d_in, const int* in_sizes, int n_in,
                              void* d_out, int out_size) {
    const float* x     = (const float*)d_in[0];
    const float* adj   = (const float*)d_in[1];
    const float* P     = (const float*)d_in[2];
    const float* W1    = (const float*)d_in[3];
    const float* b1    = (const float*)d_in[4];
    const float* W2    = (const float*)d_in[5];
    const float* b2    = (const float*)d_in[6];
    const float* W3    = (const float*)d_in[7];
    const float* b3    = (const float*)d_in[8];
    const float* lin_w = (const float*)d_in[9];
    const float* lin_b = (const float*)d_in[10];
    float* out = (float*)d_out;

    float *bufA, *bufB;
    cudaGetSymbolAddress((void**)&bufA, g_bufA);
    cudaGetSymbolAddress((void**)&bufB, g_bufB);

    k_init<<<256, 256>>>();                                     // zero bufA, init d/cnt
    k_scan<<<2048, 256>>>((const float4*)adj, P);
    k_prep<<<512, 256>>>();
    k_gemm1<<<dim3(128, 4), 240>>>(x, W1);                      // bufA += X@W1 (K-split)
    k_spmm<0><<<512, 256>>>(bufA, b1, W2, nullptr, bufB);       // bufB = relu(spmm+b1)@W2
    k_spmm<0><<<512, 256>>>(bufB, b2, W3, nullptr, bufA);       // bufA = relu(spmm+b2)@W3
    k_spmm<1><<<512, 256>>>(bufA, b3, lin_w, lin_b, out);       // log_softmax head
}

// round 10
// speedup vs baseline: 1.8730x; 1.1480x over previous
#include <cuda_runtime.h>

#define NN 4096
#define NF 512
#define NH 60
#define NC 4
#define MAXDEG 128
#define PAD 64   // padded feature stride

#define GEMM_BLOCKS 256   // 64 row-blocks x 4 K-chunks
#define SCAN_BLOCKS 2048

// ---- static device scratch (no allocations allowed) ----
__device__ float  g_d[NN];              // column sums of A_tilde (init 1.0 for self loop)
__device__ int    g_cnt[NN];            // per-row nnz count
__device__ int    g_col[NN * MAXDEG];   // raw CSR columns (from scan)
__device__ float  g_wv[NN * MAXDEG];    // raw CSR values (sigmoid(P)*adj)
__device__ float2 g_edge[NN * MAXDEG];  // prescaled edges: {bitcast(j), w*dis_i*dis_j}
__device__ float  g_self[NN];           // 1/d_i  (self-loop weight dis_i^2)
__device__ float  g_bufA[NN * PAD];
__device__ float  g_bufB[NN * PAD];

// ---------------- kernel 1: init ----------------
// Zeroes ALL of bufA (gemm accumulates into it with atomics), bufB pads,
// and resets degree/count arrays.
__global__ void k_init() {
    int t = blockIdx.x * blockDim.x + threadIdx.x;   // 65536 threads
    ((float4*)g_bufA)[t] = make_float4(0.f, 0.f, 0.f, 0.f);
    if (t < NN) {
        g_d[t] = 1.0f; g_cnt[t] = 0;
        #pragma unroll
        for (int c = NH; c < PAD; c++) g_bufB[t * PAD + c] = 0.f;
    }
}

// ---------------- kernel 2 (FAT): scan sub_adj  ||  Z0 = X @ W1 ----------------
// Blocks [0, GEMM_BLOCKS): GEMM role. 64 rows x 60 cols per block, K-chunk 128.
//   240 active compute threads: 15 col-groups (4 cols) x 16 row-groups (4 rows).
//   X staged TRANSPOSED (Xs_t[kk][row]) so both operands load as float4.
// Blocks [GEMM_BLOCKS, +SCAN_BLOCKS): scan role (DRAM-bound; overlaps with gemm).
__global__ void __launch_bounds__(256) k_fat(const float* __restrict__ X,
                                             const float* __restrict__ W1,
                                             const float4* __restrict__ adj,
                                             const float* __restrict__ P) {
    __shared__ float Xs_t[32 * 68];   // [kk][row], stride 68 (16B-aligned rows)
    __shared__ float Ws[32 * NH];     // [kk][col], flat copy of W1 chunk

    int tid = threadIdx.x;

    if (blockIdx.x < GEMM_BLOCKS) {
        // ===================== GEMM role =====================
        int rb = blockIdx.x >> 2;          // 0..63
        int ky = blockIdx.x & 3;           // 0..3
        int rowbase = rb * 64;
        int kbase = ky * 128;

        bool active = (tid < 240);
        int cg = tid % 15, rt = tid / 15;
        int c0 = cg * 4;
        int r0 = active ? rt * 4 : 0;      // idle threads read row 0 (harmless)

        float acc[4][4];
        #pragma unroll
        for (int i = 0; i < 4; i++)
            #pragma unroll
            for (int j = 0; j < 4; j++) acc[i][j] = 0.f;

        for (int s = 0; s < 4; s++) {
            int kb = kbase + s * 32;
            // stage X transposed: 64 rows x 32 k = 512 float4 global loads
            #pragma unroll
            for (int it = 0; it < 2; it++) {
                int idx = tid + it * 256;
                int r = idx & 63, k4 = idx >> 6;   // k4 0..7
                float4 g = *(const float4*)&X[(rowbase + r) * NF + kb + k4 * 4];
                Xs_t[(k4 * 4 + 0) * 68 + r] = g.x;
                Xs_t[(k4 * 4 + 1) * 68 + r] = g.y;
                Xs_t[(k4 * 4 + 2) * 68 + r] = g.z;
                Xs_t[(k4 * 4 + 3) * 68 + r] = g.w;
            }
            // stage W chunk: 32 x 60 floats = 480 float4 (256-thread strided loop)
            for (int idx = tid; idx < 480; idx += 256)
                ((float4*)Ws)[idx] = ((const float4*)&W1[kb * NH])[idx];
            __syncthreads();

            #pragma unroll 8
            for (int kk = 0; kk < 32; kk++) {
                float4 x4 = *(const float4*)&Xs_t[kk * 68 + r0];
                float4 w4 = *(const float4*)&Ws[kk * NH + c0];
                float xv[4] = {x4.x, x4.y, x4.z, x4.w};
                float wv[4] = {w4.x, w4.y, w4.z, w4.w};
                #pragma unroll
                for (int i = 0; i < 4; i++)
                    #pragma unroll
                    for (int j = 0; j < 4; j++)
                        acc[i][j] += xv[i] * wv[j];
            }
            __syncthreads();
        }
        if (active) {
            #pragma unroll
            for (int i = 0; i < 4; i++) {
                float* o = &g_bufA[(rowbase + r0 + i) * PAD + c0];
                atomicAdd(o + 0, acc[i][0]);
                atomicAdd(o + 1, acc[i][1]);
                atomicAdd(o + 2, acc[i][2]);
                atomicAdd(o + 3, acc[i][3]);
            }
        }
    } else {
        // ===================== scan role =====================
        const int T = SCAN_BLOCKS * 256;
        int t = (blockIdx.x - GEMM_BLOCKS) * 256 + tid;
        float4 a[8];
        #pragma unroll
        for (int u = 0; u < 8; u++) a[u] = adj[t + u * T];

        #pragma unroll
        for (int u = 0; u < 8; u++) {
            float4 a4 = a[u];
            if (a4.x == 0.f && a4.y == 0.f && a4.z == 0.f && a4.w == 0.f) continue;
            int base = (t + u * T) << 2;
            int i = base >> 12;
            int j0 = base & (NN - 1);
            float av[4] = {a4.x, a4.y, a4.z, a4.w};
            #pragma unroll
            for (int q = 0; q < 4; q++) {
                float aa = av[q];
                if (aa == 0.f) continue;
                int j = j0 + q;
                int tri = (i >= j) ? (i * (i + 1) / 2 + j) : (j * (j + 1) / 2 + i);
                float p = P[tri];
                float w = aa / (1.f + __expf(-p));
                atomicAdd(&g_d[j], w);
                int s = atomicAdd(&g_cnt[i], 1);
                if (s < MAXDEG) {
                    g_col[i * MAXDEG + s] = j;
                    g_wv[i * MAXDEG + s] = w;
                }
            }
        }
    }
}

// ---------------- kernel 3: prescale edges ----------------
// one warp per row: edge_w = w * rsqrt(d_i) * rsqrt(d_j); self = 1/d_i.
__global__ void __launch_bounds__(256) k_prep() {
    int tid = threadIdx.x;
    int w = tid >> 5, lane = tid & 31;
    int row = blockIdx.x * 8 + w;
    float ri = rsqrtf(g_d[row]);
    if (lane == 0) g_self[row] = ri * ri;
    int deg = min(g_cnt[row], MAXDEG);
    int base = row * MAXDEG;
    for (int e = lane; e < deg; e += 32) {
        int j = g_col[base + e];
        float ww = g_wv[base + e] * ri * rsqrtf(g_d[j]);
        g_edge[base + e] = make_float2(__int_as_float(j), ww);
    }
}

// ---------------- kernels 4-6: SpMM (+bias[,relu]) fused with next GEMM / head ----------------
// Zin/out are PAD(64)-strided; each lane owns feature cols {2*lane, 2*lane+1} as float2.
template <int MODE>
__global__ void __launch_bounds__(256) k_spmm(const float* __restrict__ Zin,
                                              const float* __restrict__ bias,
                                              const float* __restrict__ Wn,
                                              const float* __restrict__ lin_b,
                                              float* __restrict__ out) {
    __shared__ float Wsh[NH * PAD];      // zero-padded: Wsh[k*64 + c]
    __shared__ float hsh[8][PAD];
    int tid = threadIdx.x;

    if (MODE == 0) {
        for (int idx = tid; idx < NH * PAD; idx += 256) {
            int k = idx >> 6, c = idx & 63;
            Wsh[idx] = (c < NH) ? Wn[k * NH + c] : 0.f;
        }
    } else {
        for (int idx = tid; idx < NH * NC; idx += 256) Wsh[idx] = Wn[idx];
    }
    __syncthreads();

    int w = tid >> 5, lane = tid & 31;
    int row = blockIdx.x * 8 + w;
    int deg = min(g_cnt[row], MAXDEG);
    const float2* ep = g_edge + row * MAXDEG;
    const float2* Z2 = (const float2*)Zin;

    float2 acc = make_float2(0.f, 0.f);
    int e = 0;
    for (; e + 4 <= deg; e += 4) {
        float2 q0 = ep[e], q1 = ep[e + 1], q2 = ep[e + 2], q3 = ep[e + 3];
        int j0 = __float_as_int(q0.x), j1 = __float_as_int(q1.x);
        int j2 = __float_as_int(q2.x), j3 = __float_as_int(q3.x);
        float2 z0 = Z2[j0 * 32 + lane];
        float2 z1 = Z2[j1 * 32 + lane];
        float2 z2 = Z2[j2 * 32 + lane];
        float2 z3 = Z2[j3 * 32 + lane];
        acc.x += q0.y * z0.x + q1.y * z1.x + q2.y * z2.x + q3.y * z3.x;
        acc.y += q0.y * z0.y + q1.y * z1.y + q2.y * z2.y + q3.y * z3.y;
    }
    for (; e < deg; e++) {
        float2 q = ep[e];
        int j = __float_as_int(q.x);
        float2 z = Z2[j * 32 + lane];
        acc.x += q.y * z.x;
        acc.y += q.y * z.y;
    }

    float2 h = make_float2(0.f, 0.f);
    if (lane < NH / 2) {
        float sw = g_self[row];
        float2 zr = Z2[row * 32 + lane];
        float2 bi = ((const float2*)bias)[lane];
        h.x = acc.x + sw * zr.x + bi.x;
        h.y = acc.y + sw * zr.y + bi.y;
        if (MODE == 0) { h.x = fmaxf(h.x, 0.f); h.y = fmaxf(h.y, 0.f); }
    }
    *(float2*)&hsh[w][2 * lane] = h;
    __syncwarp();

    if (MODE == 0) {
        const float2* Wsh2 = (const float2*)Wsh;
        float2 z = make_float2(0.f, 0.f);
        #pragma unroll
        for (int k = 0; k < NH; k++) {
            float hk = hsh[w][k];               // broadcast
            float2 wv = Wsh2[k * 32 + lane];    // conflict-free, pad lanes read zeros
            z.x += hk * wv.x;
            z.y += hk * wv.y;
        }
        ((float2*)out)[row * 32 + lane] = z;    // pad lanes write zeros
    } else {
        float logit = 0.f;
        if (lane < NC) {
            logit = lin_b[lane];
            #pragma unroll
            for (int k = 0; k < NH; k++) logit += hsh[w][k] * Wsh[k * NC + lane];
        }
        float l0 = __shfl_sync(0xffffffffu, logit, 0);
        float l1 = __shfl_sync(0xffffffffu, logit, 1);
        float l2 = __shfl_sync(0xffffffffu, logit, 2);
        float l3 = __shfl_sync(0xffffffffu, logit, 3);
        if (lane < NC) {
            float m = fmaxf(fmaxf(l0, l1), fmaxf(l2, l3));
            float s = __expf(l0 - m) + __expf(l1 - m) + __expf(l2 - m) + __expf(l3 - m);
            out[row * NC + lane] = logit - m - logf(s);
        }
    }
}

// ---------------- launch ----------------
extern "C" void kernel_launch(void* const* d_in, const int* in_sizes, int n_in,
                              void* d_out, int out_size) {
    const float* x     = (const float*)d_in[0];
    const float* adj   = (const float*)d_in[1];
    const float* P     = (const float*)d_in[2];
    const float* W1    = (const float*)d_in[3];
    const float* b1    = (const float*)d_in[4];
    const float* W2    = (const float*)d_in[5];
    const float* b2    = (const float*)d_in[6];
    const float* W3    = (const float*)d_in[7];
    const float* b3    = (const float*)d_in[8];
    const float* lin_w = (const float*)d_in[9];
    const float* lin_b = (const float*)d_in[10];
    float* out = (float*)d_out;

    float *bufA, *bufB;
    cudaGetSymbolAddress((void**)&bufA, g_bufA);
    cudaGetSymbolAddress((void**)&bufB, g_bufB);

    k_init<<<256, 256>>>();                                     // zero bufA, init d/cnt
    k_fat<<<GEMM_BLOCKS + SCAN_BLOCKS, 256>>>(x, W1, (const float4*)adj, P);
    k_prep<<<512, 256>>>();
    k_spmm<0><<<512, 256>>>(bufA, b1, W2, nullptr, bufB);       // bufB = relu(spmm+b1)@W2
    k_spmm<0><<<512, 256>>>(bufB, b2, W3, nullptr, bufA);       // bufA = relu(spmm+b2)@W3
    k_spmm<1><<<512, 256>>>(bufA, b3, lin_w, lin_b, out);       // log_softmax head
}

// round 11
// speedup vs baseline: 2.0616x; 1.1007x over previous
#include <cuda_runtime.h>

#define NN 4096
#define NF 512
#define NH 60
#define NC 4
#define MAXDEG 128
#define PAD 64   // padded feature stride

#define GEMM_BLOCKS 256   // 64 row-blocks x 4 K-chunks
#define SCAN_BLOCKS 2048

// ---- static device scratch (no allocations allowed) ----
__device__ float  g_d[NN];              // column sums of A_tilde (init 1.0 for self loop)
__device__ int    g_cnt[NN];            // per-row nnz count
__device__ int    g_degp[NN];           // padded degree (multiple of 4)
__device__ int    g_col[NN * MAXDEG];   // raw CSR columns (from scan)
__device__ float  g_wv[NN * MAXDEG];    // raw CSR values (sigmoid(P)*adj)
__device__ float2 g_edge[NN * MAXDEG];  // prescaled edges: {bitcast(j), w*dis_i*dis_j}
__device__ float  g_self[NN];           // 1/d_i  (self-loop weight dis_i^2)
__device__ float  g_bufA[NN * PAD];
__device__ float  g_bufB[NN * PAD];

// ---------------- kernel 1: init ----------------
__global__ void k_init() {
    int t = blockIdx.x * blockDim.x + threadIdx.x;   // 65536 threads
    ((float4*)g_bufA)[t] = make_float4(0.f, 0.f, 0.f, 0.f);
    if (t < NN) {
        g_d[t] = 1.0f; g_cnt[t] = 0;
        #pragma unroll
        for (int c = NH; c < PAD; c++) g_bufB[t * PAD + c] = 0.f;
    }
}

// ---------------- kernel 2 (FAT): scan sub_adj  ||  Z0 = X @ W1 ----------------
__global__ void __launch_bounds__(256) k_fat(const float* __restrict__ X,
                                             const float* __restrict__ W1,
                                             const float4* __restrict__ adj,
                                             const float* __restrict__ P) {
    __shared__ float Xs_t[32 * 68];   // [kk][row], stride 68
    __shared__ float Ws[32 * NH];     // [kk][col]

    int tid = threadIdx.x;

    if (blockIdx.x < GEMM_BLOCKS) {
        // ===================== GEMM role =====================
        int rb = blockIdx.x >> 2;
        int ky = blockIdx.x & 3;
        int rowbase = rb * 64;
        int kbase = ky * 128;

        bool active = (tid < 240);
        int cg = tid % 15, rt = tid / 15;
        int c0 = cg * 4;
        int r0 = active ? rt * 4 : 0;

        float acc[4][4];
        #pragma unroll
        for (int i = 0; i < 4; i++)
            #pragma unroll
            for (int j = 0; j < 4; j++) acc[i][j] = 0.f;

        for (int s = 0; s < 4; s++) {
            int kb = kbase + s * 32;
            #pragma unroll
            for (int it = 0; it < 2; it++) {
                int idx = tid + it * 256;
                int r = idx & 63, k4 = idx >> 6;
                float4 g = *(const float4*)&X[(rowbase + r) * NF + kb + k4 * 4];
                Xs_t[(k4 * 4 + 0) * 68 + r] = g.x;
                Xs_t[(k4 * 4 + 1) * 68 + r] = g.y;
                Xs_t[(k4 * 4 + 2) * 68 + r] = g.z;
                Xs_t[(k4 * 4 + 3) * 68 + r] = g.w;
            }
            for (int idx = tid; idx < 480; idx += 256)
                ((float4*)Ws)[idx] = ((const float4*)&W1[kb * NH])[idx];
            __syncthreads();

            #pragma unroll 8
            for (int kk = 0; kk < 32; kk++) {
                float4 x4 = *(const float4*)&Xs_t[kk * 68 + r0];
                float4 w4 = *(const float4*)&Ws[kk * NH + c0];
                float xv[4] = {x4.x, x4.y, x4.z, x4.w};
                float wv[4] = {w4.x, w4.y, w4.z, w4.w};
                #pragma unroll
                for (int i = 0; i < 4; i++)
                    #pragma unroll
                    for (int j = 0; j < 4; j++)
                        acc[i][j] += xv[i] * wv[j];
            }
            __syncthreads();
        }
        if (active) {
            #pragma unroll
            for (int i = 0; i < 4; i++) {
                float* o = &g_bufA[(rowbase + r0 + i) * PAD + c0];
                atomicAdd(o + 0, acc[i][0]);
                atomicAdd(o + 1, acc[i][1]);
                atomicAdd(o + 2, acc[i][2]);
                atomicAdd(o + 3, acc[i][3]);
            }
        }
    } else {
        // ===================== scan role =====================
        const int T = SCAN_BLOCKS * 256;
        int t = (blockIdx.x - GEMM_BLOCKS) * 256 + tid;
        float4 a[8];
        #pragma unroll
        for (int u = 0; u < 8; u++) a[u] = adj[t + u * T];

        #pragma unroll
        for (int u = 0; u < 8; u++) {
            float4 a4 = a[u];
            if (a4.x == 0.f && a4.y == 0.f && a4.z == 0.f && a4.w == 0.f) continue;
            int base = (t + u * T) << 2;
            int i = base >> 12;
            int j0 = base & (NN - 1);
            float av[4] = {a4.x, a4.y, a4.z, a4.w};
            #pragma unroll
            for (int q = 0; q < 4; q++) {
                float aa = av[q];
                if (aa == 0.f) continue;
                int j = j0 + q;
                int tri = (i >= j) ? (i * (i + 1) / 2 + j) : (j * (j + 1) / 2 + i);
                float p = P[tri];
                float w = aa / (1.f + __expf(-p));
                atomicAdd(&g_d[j], w);
                int s = atomicAdd(&g_cnt[i], 1);
                if (s < MAXDEG) {
                    g_col[i * MAXDEG + s] = j;
                    g_wv[i * MAXDEG + s] = w;
                }
            }
        }
    }
}

// ---------------- kernel 3: prescale edges + pad to multiple of 4 ----------------
__global__ void __launch_bounds__(256) k_prep() {
    int tid = threadIdx.x;
    int w = tid >> 5, lane = tid & 31;
    int row = blockIdx.x * 8 + w;
    float ri = rsqrtf(g_d[row]);
    int deg = min(g_cnt[row], MAXDEG);
    int padded = (deg + 3) & ~3;
    if (lane == 0) { g_self[row] = ri * ri; g_degp[row] = padded; }
    int base = row * MAXDEG;
    for (int e = lane; e < padded; e += 32) {
        if (e < deg) {
            int j = g_col[base + e];
            float ww = g_wv[base + e] * ri * rsqrtf(g_d[j]);
            g_edge[base + e] = make_float2(__int_as_float(j), ww);
        } else {
            g_edge[base + e] = make_float2(__int_as_float(0), 0.f);
        }
    }
}

// ---------------- kernels 4-6: SpMM (+bias[,relu]) fused with next GEMM / head ----------------
// 2 rows per warp, 16 rows per block (grid 256). Zin/out PAD(64)-strided;
// lane owns feature cols {2*lane, 2*lane+1} as float2. Wsh staged verbatim
// (stride NH); pad-lane reads/writes are harmless (masked h, unused pad cols).
template <int MODE>
__global__ void __launch_bounds__(256) k_spmm(const float* __restrict__ Zin,
                                              const float* __restrict__ bias,
                                              const float* __restrict__ Wn,
                                              const float* __restrict__ lin_b,
                                              float* __restrict__ out) {
    __shared__ float Wsh[NH * NH + 64];  // verbatim Wn copy (+ overrun slack)
    __shared__ float hsh[16][PAD];
    int tid = threadIdx.x;

    const int w4 = (MODE == 0) ? (NH * NH / 4) : (NH * NC / 4);
    for (int idx = tid; idx < w4; idx += 256)
        ((float4*)Wsh)[idx] = ((const float4*)Wn)[idx];
    __syncthreads();

    int w = tid >> 5, lane = tid & 31;
    int rowA = blockIdx.x * 16 + w * 2;
    int rowB = rowA + 1;
    const float2* Z2 = (const float2*)Zin;

    int degA = g_degp[rowA], degB = g_degp[rowB];
    const float2* epA = g_edge + rowA * MAXDEG;
    const float2* epB = g_edge + rowB * MAXDEG;

    float2 accA = make_float2(0.f, 0.f);
    float2 accB = make_float2(0.f, 0.f);
    int dmax = max(degA, degB);
    for (int e = 0; e < dmax; e += 4) {
        if (e < degA) {
            float2 q0 = epA[e], q1 = epA[e + 1], q2 = epA[e + 2], q3 = epA[e + 3];
            float2 z0 = Z2[__float_as_int(q0.x) * 32 + lane];
            float2 z1 = Z2[__float_as_int(q1.x) * 32 + lane];
            float2 z2 = Z2[__float_as_int(q2.x) * 32 + lane];
            float2 z3 = Z2[__float_as_int(q3.x) * 32 + lane];
            accA.x += q0.y * z0.x + q1.y * z1.x + q2.y * z2.x + q3.y * z3.x;
            accA.y += q0.y * z0.y + q1.y * z1.y + q2.y * z2.y + q3.y * z3.y;
        }
        if (e < degB) {
            float2 q0 = epB[e], q1 = epB[e + 1], q2 = epB[e + 2], q3 = epB[e + 3];
            float2 z0 = Z2[__float_as_int(q0.x) * 32 + lane];
            float2 z1 = Z2[__float_as_int(q1.x) * 32 + lane];
            float2 z2 = Z2[__float_as_int(q2.x) * 32 + lane];
            float2 z3 = Z2[__float_as_int(q3.x) * 32 + lane];
            accB.x += q0.y * z0.x + q1.y * z1.x + q2.y * z2.x + q3.y * z3.x;
            accB.y += q0.y * z0.y + q1.y * z1.y + q2.y * z2.y + q3.y * z3.y;
        }
    }

    float2 hA = make_float2(0.f, 0.f), hB = make_float2(0.f, 0.f);
    if (lane < NH / 2) {
        float2 bi = ((const float2*)bias)[lane];
        float sA = g_self[rowA], sB = g_self[rowB];
        float2 zrA = Z2[rowA * 32 + lane];
        float2 zrB = Z2[rowB * 32 + lane];
        hA.x = accA.x + sA * zrA.x + bi.x;
        hA.y = accA.y + sA * zrA.y + bi.y;
        hB.x = accB.x + sB * zrB.x + bi.x;
        hB.y = accB.y + sB * zrB.y + bi.y;
        if (MODE == 0) {
            hA.x = fmaxf(hA.x, 0.f); hA.y = fmaxf(hA.y, 0.f);
            hB.x = fmaxf(hB.x, 0.f); hB.y = fmaxf(hB.y, 0.f);
        }
    }
    *(float2*)&hsh[w * 2][2 * lane] = hA;
    *(float2*)&hsh[w * 2 + 1][2 * lane] = hB;
    __syncwarp();

    if (MODE == 0) {
        float2 zA = make_float2(0.f, 0.f), zB = make_float2(0.f, 0.f);
        #pragma unroll
        for (int k = 0; k < NH; k++) {
            float2 wv = *(const float2*)&Wsh[k * NH + 2 * lane];  // conflict-free
            float ha = hsh[w * 2][k];                              // broadcast
            float hb = hsh[w * 2 + 1][k];                          // broadcast
            zA.x += ha * wv.x; zA.y += ha * wv.y;
            zB.x += hb * wv.x; zB.y += hb * wv.y;
        }
        ((float2*)out)[rowA * 32 + lane] = zA;
        ((float2*)out)[rowB * 32 + lane] = zB;
    } else {
        float logitA = 0.f, logitB = 0.f;
        if (lane < NC) {
            logitA = lin_b[lane];
            logitB = lin_b[lane];
            #pragma unroll
            for (int k = 0; k < NH; k++) {
                float wv = Wsh[k * NC + lane];
                logitA += hsh[w * 2][k] * wv;
                logitB += hsh[w * 2 + 1][k] * wv;
            }
        }
        #pragma unroll
        for (int rr = 0; rr < 2; rr++) {
            float logit = (rr == 0) ? logitA : logitB;
            float l0 = __shfl_sync(0xffffffffu, logit, 0);
            float l1 = __shfl_sync(0xffffffffu, logit, 1);
            float l2 = __shfl_sync(0xffffffffu, logit, 2);
            float l3 = __shfl_sync(0xffffffffu, logit, 3);
            if (lane < NC) {
                float m = fmaxf(fmaxf(l0, l1), fmaxf(l2, l3));
                float s = __expf(l0 - m) + __expf(l1 - m) + __expf(l2 - m) + __expf(l3 - m);
                out[(rowA + rr) * NC + lane] = logit - m - logf(s);
            }
        }
    }
}

// ---------------- launch ----------------
extern "C" void kernel_launch(void* const* d_in, const int* in_sizes, int n_in,
                              void* d_out, int out_size) {
    const float* x     = (const float*)d_in[0];
    const float* adj   = (const float*)d_in[1];
    const float* P     = (const float*)d_in[2];
    const float* W1    = (const float*)d_in[3];
    const float* b1    = (const float*)d_in[4];
    const float* W2    = (const float*)d_in[5];
    const float* b2    = (const float*)d_in[6];
    const float* W3    = (const float*)d_in[7];
    const float* b3    = (const float*)d_in[8];
    const float* lin_w = (const float*)d_in[9];
    const float* lin_b = (const float*)d_in[10];
    float* out = (float*)d_out;

    float *bufA, *bufB;
    cudaGetSymbolAddress((void**)&bufA, g_bufA);
    cudaGetSymbolAddress((void**)&bufB, g_bufB);

    k_init<<<256, 256>>>();                                     // zero bufA, init d/cnt
    k_fat<<<GEMM_BLOCKS + SCAN_BLOCKS, 256>>>(x, W1, (const float4*)adj, P);
    k_prep<<<512, 256>>>();
    k_spmm<0><<<256, 256>>>(bufA, b1, W2, nullptr, bufB);       // bufB = relu(spmm+b1)@W2
    k_spmm<0><<<256, 256>>>(bufB, b2, W3, nullptr, bufA);       // bufA = relu(spmm+b2)@W3
    k_spmm<1><<<256, 256>>>(bufA, b3, lin_w, lin_b, out);       // log_softmax head
}

// round 12
// speedup vs baseline: 2.0727x; 1.0054x over previous
#include <cuda_runtime.h>

#define NN 4096
#define NF 512
#define NH 60
#define NC 4
#define MAXDEG 128
#define PAD 64   // padded feature stride

#define GEMM_BLOCKS 256   // 64 row-blocks x 4 K-chunks
#define SCAN_BLOCKS 2048

// ---- static device scratch (no allocations allowed) ----
__device__ float  g_d[NN];              // column sums of A_tilde (init 1.0 for self loop)
__device__ int    g_cnt[NN];            // per-row nnz count
__device__ int    g_degp[NN];           // padded degree (multiple of 8)
__device__ int    g_col[NN * MAXDEG];   // raw CSR columns (from scan)
__device__ float  g_wv[NN * MAXDEG];    // raw CSR values (sigmoid(P)*adj)
__device__ float2 g_edge[NN * MAXDEG];  // prescaled edges: {bitcast(j), w*dis_i*dis_j}
__device__ float  g_self[NN];           // 1/d_i  (self-loop weight dis_i^2)
__device__ float  g_bufA[NN * PAD];
__device__ float  g_bufB[NN * PAD];

// ---------------- kernel 1: init (bufA zeroed separately via memsetAsync) ----------------
__global__ void k_init() {
    int t = blockIdx.x * blockDim.x + threadIdx.x;
    if (t < NN) { g_d[t] = 1.0f; g_cnt[t] = 0; }
}

// ---------------- kernel 2 (FAT): scan sub_adj  ||  Z0 = X @ W1 ----------------
__global__ void __launch_bounds__(256) k_fat(const float* __restrict__ X,
                                             const float* __restrict__ W1,
                                             const float4* __restrict__ adj,
                                             const float* __restrict__ P) {
    __shared__ float Xs_t[32 * 68];   // [kk][row], stride 68
    __shared__ float Ws[32 * NH];     // [kk][col]

    int tid = threadIdx.x;

    if (blockIdx.x < GEMM_BLOCKS) {
        // ===================== GEMM role =====================
        int rb = blockIdx.x >> 2;
        int ky = blockIdx.x & 3;
        int rowbase = rb * 64;
        int kbase = ky * 128;

        bool active = (tid < 240);
        int cg = tid % 15, rt = tid / 15;
        int c0 = cg * 4;
        int r0 = active ? rt * 4 : 0;

        float acc[4][4];
        #pragma unroll
        for (int i = 0; i < 4; i++)
            #pragma unroll
            for (int j = 0; j < 4; j++) acc[i][j] = 0.f;

        for (int s = 0; s < 4; s++) {
            int kb = kbase + s * 32;
            #pragma unroll
            for (int it = 0; it < 2; it++) {
                int idx = tid + it * 256;
                int r = idx & 63, k4 = idx >> 6;
                float4 g = *(const float4*)&X[(rowbase + r) * NF + kb + k4 * 4];
                Xs_t[(k4 * 4 + 0) * 68 + r] = g.x;
                Xs_t[(k4 * 4 + 1) * 68 + r] = g.y;
                Xs_t[(k4 * 4 + 2) * 68 + r] = g.z;
                Xs_t[(k4 * 4 + 3) * 68 + r] = g.w;
            }
            for (int idx = tid; idx < 480; idx += 256)
                ((float4*)Ws)[idx] = ((const float4*)&W1[kb * NH])[idx];
            __syncthreads();

            #pragma unroll 8
            for (int kk = 0; kk < 32; kk++) {
                float4 x4 = *(const float4*)&Xs_t[kk * 68 + r0];
                float4 w4 = *(const float4*)&Ws[kk * NH + c0];
                float xv[4] = {x4.x, x4.y, x4.z, x4.w};
                float wv[4] = {w4.x, w4.y, w4.z, w4.w};
                #pragma unroll
                for (int i = 0; i < 4; i++)
                    #pragma unroll
                    for (int j = 0; j < 4; j++)
                        acc[i][j] += xv[i] * wv[j];
            }
            __syncthreads();
        }
        if (active) {
            #pragma unroll
            for (int i = 0; i < 4; i++) {
                float* o = &g_bufA[(rowbase + r0 + i) * PAD + c0];
                atomicAdd(o + 0, acc[i][0]);
                atomicAdd(o + 1, acc[i][1]);
                atomicAdd(o + 2, acc[i][2]);
                atomicAdd(o + 3, acc[i][3]);
            }
        }
    } else {
        // ===================== scan role =====================
        const int T = SCAN_BLOCKS * 256;
        int t = (blockIdx.x - GEMM_BLOCKS) * 256 + tid;
        float4 a[8];
        #pragma unroll
        for (int u = 0; u < 8; u++) a[u] = adj[t + u * T];

        #pragma unroll
        for (int u = 0; u < 8; u++) {
            float4 a4 = a[u];
            if (a4.x == 0.f && a4.y == 0.f && a4.z == 0.f && a4.w == 0.f) continue;
            int base = (t + u * T) << 2;
            int i = base >> 12;
            int j0 = base & (NN - 1);
            float av[4] = {a4.x, a4.y, a4.z, a4.w};
            #pragma unroll
            for (int q = 0; q < 4; q++) {
                float aa = av[q];
                if (aa == 0.f) continue;
                int j = j0 + q;
                int tri = (i >= j) ? (i * (i + 1) / 2 + j) : (j * (j + 1) / 2 + i);
                float p = P[tri];
                float w = aa / (1.f + __expf(-p));
                atomicAdd(&g_d[j], w);
                int s = atomicAdd(&g_cnt[i], 1);
                if (s < MAXDEG) {
                    g_col[i * MAXDEG + s] = j;
                    g_wv[i * MAXDEG + s] = w;
                }
            }
        }
    }
}

// ---------------- kernel 3: prescale edges + pad to multiple of 8 ----------------
__global__ void __launch_bounds__(256) k_prep() {
    int tid = threadIdx.x;
    int w = tid >> 5, lane = tid & 31;
    int row = blockIdx.x * 8 + w;
    float ri = rsqrtf(g_d[row]);
    int deg = min(g_cnt[row], MAXDEG);
    int padded = (deg + 7) & ~7;
    if (lane == 0) { g_self[row] = ri * ri; g_degp[row] = padded; }
    int base = row * MAXDEG;
    for (int e = lane; e < padded; e += 32) {
        if (e < deg) {
            int j = g_col[base + e];
            float ww = g_wv[base + e] * ri * rsqrtf(g_d[j]);
            g_edge[base + e] = make_float2(__int_as_float(j), ww);
        } else {
            g_edge[base + e] = make_float2(__int_as_float(0), 0.f);
        }
    }
}

// ---------------- kernels 4-6: SpMM (+bias[,relu]) fused with next GEMM / head ----------------
// 1 row per warp, 8 rows per block (grid 512). Batch-8 edge processing:
// 8 independent edge loads, then 8 independent row-gathers per iteration.
// Zin/out PAD(64)-strided; lane owns feature cols {2*lane, 2*lane+1} as float2.
// Wsh staged verbatim (stride NH); pad-lane reads/writes provably harmless
// (pad h is masked to 0, pad output columns never consumed with nonzero weight).
template <int MODE>
__global__ void __launch_bounds__(256) k_spmm(const float* __restrict__ Zin,
                                              const float* __restrict__ bias,
                                              const float* __restrict__ Wn,
                                              const float* __restrict__ lin_b,
                                              float* __restrict__ out) {
    __shared__ float Wsh[NH * NH + 64];  // verbatim Wn copy (+ overrun slack)
    __shared__ float hsh[8][PAD];
    int tid = threadIdx.x;

    const int w4 = (MODE == 0) ? (NH * NH / 4) : (NH * NC / 4);
    for (int idx = tid; idx < w4; idx += 256)
        ((float4*)Wsh)[idx] = ((const float4*)Wn)[idx];
    __syncthreads();

    int w = tid >> 5, lane = tid & 31;
    int row = blockIdx.x * 8 + w;
    const float2* Z2 = (const float2*)Zin;

    int deg = g_degp[row];
    const float2* ep = g_edge + row * MAXDEG;

    float2 acc = make_float2(0.f, 0.f);
    for (int e = 0; e < deg; e += 8) {
        float2 q[8];
        #pragma unroll
        for (int u = 0; u < 8; u++) q[u] = ep[e + u];
        float2 z[8];
        #pragma unroll
        for (int u = 0; u < 8; u++) z[u] = Z2[__float_as_int(q[u].x) * 32 + lane];
        #pragma unroll
        for (int u = 0; u < 8; u++) {
            acc.x += q[u].y * z[u].x;
            acc.y += q[u].y * z[u].y;
        }
    }

    float2 h = make_float2(0.f, 0.f);
    if (lane < NH / 2) {
        float2 bi = ((const float2*)bias)[lane];
        float sw = g_self[row];
        float2 zr = Z2[row * 32 + lane];
        h.x = acc.x + sw * zr.x + bi.x;
        h.y = acc.y + sw * zr.y + bi.y;
        if (MODE == 0) { h.x = fmaxf(h.x, 0.f); h.y = fmaxf(h.y, 0.f); }
    }
    *(float2*)&hsh[w][2 * lane] = h;
    __syncwarp();

    if (MODE == 0) {
        float2 z = make_float2(0.f, 0.f);
        #pragma unroll
        for (int k = 0; k < NH; k++) {
            float2 wv = *(const float2*)&Wsh[k * NH + 2 * lane];  // conflict-free
            float hk = hsh[w][k];                                  // broadcast
            z.x += hk * wv.x;
            z.y += hk * wv.y;
        }
        ((float2*)out)[row * 32 + lane] = z;
    } else {
        float logit = 0.f;
        if (lane < NC) {
            logit = lin_b[lane];
            #pragma unroll
            for (int k = 0; k < NH; k++) logit += hsh[w][k] * Wsh[k * NC + lane];
        }
        float l0 = __shfl_sync(0xffffffffu, logit, 0);
        float l1 = __shfl_sync(0xffffffffu, logit, 1);
        float l2 = __shfl_sync(0xffffffffu, logit, 2);
        float l3 = __shfl_sync(0xffffffffu, logit, 3);
        if (lane < NC) {
            float m = fmaxf(fmaxf(l0, l1), fmaxf(l2, l3));
            float s = __expf(l0 - m) + __expf(l1 - m) + __expf(l2 - m) + __expf(l3 - m);
            out[row * NC + lane] = logit - m - logf(s);
        }
    }
}

// ---------------- launch ----------------
extern "C" void kernel_launch(void* const* d_in, const int* in_sizes, int n_in,
                              void* d_out, int out_size) {
    const float* x     = (const float*)d_in[0];
    const float* adj   = (const float*)d_in[1];
    const float* P     = (const float*)d_in[2];
    const float* W1    = (const float*)d_in[3];
    const float* b1    = (const float*)d_in[4];
    const float* W2    = (const float*)d_in[5];
    const float* b2    = (const float*)d_in[6];
    const float* W3    = (const float*)d_in[7];
    const float* b3    = (const float*)d_in[8];
    const float* lin_w = (const float*)d_in[9];
    const float* lin_b = (const float*)d_in[10];
    float* out = (float*)d_out;

    float *bufA, *bufB;
    cudaGetSymbolAddress((void**)&bufA, g_bufA);
    cudaGetSymbolAddress((void**)&bufB, g_bufB);

    cudaMemsetAsync(bufA, 0, NN * PAD * sizeof(float));         // gemm accumulator
    k_init<<<16, 256>>>();                                      // g_d=1, g_cnt=0
    k_fat<<<GEMM_BLOCKS + SCAN_BLOCKS, 256>>>(x, W1, (const float4*)adj, P);
    k_prep<<<512, 256>>>();
    k_spmm<0><<<512, 256>>>(bufA, b1, W2, nullptr, bufB);       // bufB = relu(spmm+b1)@W2
    k_spmm<0><<<512, 256>>>(bufB, b2, W3, nullptr, bufA);       // bufA = relu(spmm+b2)@W3
    k_spmm<1><<<512, 256>>>(bufA, b3, lin_w, lin_b, out);       // log_softmax head
}